// round 1
// baseline (speedup 1.0000x reference)
#include <cuda_runtime.h>
#include <math.h>

// ---------------- problem constants ----------------
#define NMAX 100000
#define EMAX 500000
#define FIN  512
#define NH   128

// ---------------- device scratch (static, no allocs) ----------------
__device__ __align__(16) float g_xw [NMAX * 256];   // [xl | xr] per node
__device__ __align__(16) float g_h  [NMAX * NH];    // sage output (post relu)
__device__ __align__(16) float g_agg[NMAX * NH];    // neighbor aggregate
__device__ float g_cnt [NMAX];
__device__ float g_s   [NMAX];                       // gcn xw scalar
__device__ float g_dis [NMAX];                       // rsqrt(deg)
__device__ float g_sagg[NMAX];
__device__ float g_score[NMAX];
__device__ int   g_rank[NMAX];
__device__ int   g_perm[NMAX];
__device__ __align__(16) float g_hk[20000 * NH];     // pooled features (max K1)
__device__ int g_esrc2[EMAX], g_edst2[EMAX];
__device__ int g_esrc3[EMAX], g_edst3[EMAX];
__device__ float g_pool[3 * 256];                    // x1,x2,x3 : [max128|mean128]

// radix-select / counters
__device__ unsigned g_hist[256];
__device__ unsigned g_prefix;
__device__ int g_kremain, g_tieneed, g_selpos, g_tietick;
__device__ int g_ecnt[4];   // [0]=E (layer1), [1]=after pool1, [2]=after pool2

// ---------------- utility kernels ----------------
__global__ void k_init(int E) {
    if (blockIdx.x == 0 && threadIdx.x == 0) {
        g_ecnt[0] = E; g_ecnt[1] = 0; g_ecnt[2] = 0; g_ecnt[3] = 0;
    }
}

__global__ void k_zero_f(float* p, int n) {
    for (int i = blockIdx.x * blockDim.x + threadIdx.x; i < n; i += gridDim.x * blockDim.x)
        p[i] = 0.0f;
}

__global__ void k_fill_i(int* p, int v, int n) {
    for (int i = blockIdx.x * blockDim.x + threadIdx.x; i < n; i += gridDim.x * blockDim.x)
        p[i] = v;
}

// ---------------- fp32 GEMM: C[:,0:128]=A@B1, C[:,128:256]=A@B2 ----------------
// A row-major [M,K] (ld=K), B row-major [K,128], C row-major [M,256]
__global__ __launch_bounds__(256)
void k_sgemm(const float* __restrict__ A, const float* __restrict__ B1,
             const float* __restrict__ B2, float* __restrict__ C,
             int M, int K) {
    __shared__ float As[8][128];
    __shared__ float Bs[8][128];

    const float* B = (blockIdx.y == 0) ? B1 : B2;
    const int bm  = blockIdx.x * 128;
    const int tid = threadIdx.x;
    const int tx  = tid & 15;      // 0..15 -> 8 cols each
    const int ty  = tid >> 4;      // 0..15 -> 8 rows each

    // global load assignments
    const int arow = tid >> 1;            // 0..127
    const int ak   = (tid & 1) * 4;       // 0 or 4
    const int brow = tid >> 5;            // 0..7
    const int bcol = (tid & 31) * 4;      // 0..124

    const int gm = bm + arow;
    const bool avalid = (gm < M);

    float acc[8][8];
#pragma unroll
    for (int i = 0; i < 8; i++)
#pragma unroll
        for (int j = 0; j < 8; j++) acc[i][j] = 0.0f;

    for (int k0 = 0; k0 < K; k0 += 8) {
        float4 av = avalid ? *(const float4*)(A + (size_t)gm * K + k0 + ak)
                           : make_float4(0.f, 0.f, 0.f, 0.f);
        float4 bv = *(const float4*)(B + (size_t)(k0 + brow) * 128 + bcol);
        __syncthreads();
        As[ak + 0][arow] = av.x; As[ak + 1][arow] = av.y;
        As[ak + 2][arow] = av.z; As[ak + 3][arow] = av.w;
        *(float4*)&Bs[brow][bcol] = bv;
        __syncthreads();
#pragma unroll
        for (int kk = 0; kk < 8; kk++) {
            float4 a0 = *(const float4*)&As[kk][ty * 8];
            float4 a1 = *(const float4*)&As[kk][ty * 8 + 4];
            float4 b0 = *(const float4*)&Bs[kk][tx * 8];
            float4 b1 = *(const float4*)&Bs[kk][tx * 8 + 4];
            float a[8] = {a0.x, a0.y, a0.z, a0.w, a1.x, a1.y, a1.z, a1.w};
            float b[8] = {b0.x, b0.y, b0.z, b0.w, b1.x, b1.y, b1.z, b1.w};
#pragma unroll
            for (int i = 0; i < 8; i++)
#pragma unroll
                for (int j = 0; j < 8; j++) acc[i][j] += a[i] * b[j];
        }
    }

    const int n0 = blockIdx.y * 128 + tx * 8;
#pragma unroll
    for (int i = 0; i < 8; i++) {
        int m = bm + ty * 8 + i;
        if (m < M) {
            float4 c0 = make_float4(acc[i][0], acc[i][1], acc[i][2], acc[i][3]);
            float4 c1 = make_float4(acc[i][4], acc[i][5], acc[i][6], acc[i][7]);
            *(float4*)&C[(size_t)m * 256 + n0]     = c0;
            *(float4*)&C[(size_t)m * 256 + n0 + 4] = c1;
        }
    }
}

// ---------------- SAGE neighbor aggregation (128-dim, post-GEMM) ----------------
__global__ void k_sage_agg(const int* __restrict__ src, const int* __restrict__ dst,
                           int cidx, const float* __restrict__ xw,
                           float* __restrict__ agg, float* __restrict__ cnt) {
    long total = (long)g_ecnt[cidx] * 32;
    long stride = (long)gridDim.x * blockDim.x;
    for (long idx = (long)blockIdx.x * blockDim.x + threadIdx.x; idx < total; idx += stride) {
        int e = (int)(idx >> 5);
        int c = (int)(idx & 31) << 2;
        int s = src[e], d = dst[e];
        float4 v = *(const float4*)(xw + (size_t)s * 256 + c);
        float* p = agg + (size_t)d * 128 + c;
        atomicAdd(p + 0, v.x); atomicAdd(p + 1, v.y);
        atomicAdd(p + 2, v.z); atomicAdd(p + 3, v.w);
        if (c == 0) atomicAdd(cnt + d, 1.0f);
    }
}

// ---------------- h = relu(agg/max(cnt,1)+bl+xr); s = h.gw; dis = rsqrt(cnt+1) ----------------
__global__ void k_h_fin(const float* __restrict__ agg, const float* __restrict__ cnt,
                        const float* __restrict__ xw, const float* __restrict__ bl,
                        const float* __restrict__ gw, float* __restrict__ h,
                        float* __restrict__ s, float* __restrict__ dis, int n) {
    int w = (blockIdx.x * blockDim.x + threadIdx.x) >> 5;
    int lane = threadIdx.x & 31;
    if (w >= n) return;
    float c = cnt[w];
    float inv = 1.0f / fmaxf(c, 1.0f);
    float part = 0.0f;
#pragma unroll
    for (int f = lane; f < 128; f += 32) {
        float v = agg[(size_t)w * 128 + f] * inv + bl[f] + xw[(size_t)w * 256 + 128 + f];
        v = fmaxf(v, 0.0f);
        h[(size_t)w * 128 + f] = v;
        part += v * gw[f];
    }
#pragma unroll
    for (int o = 16; o; o >>= 1) part += __shfl_down_sync(0xffffffffu, part, o);
    if (lane == 0) { s[w] = part; dis[w] = rsqrtf(c + 1.0f); }
}

// ---------------- GCN score edge pass ----------------
__global__ void k_gcn_edge(const int* __restrict__ src, const int* __restrict__ dst,
                           int cidx, const float* __restrict__ s,
                           const float* __restrict__ dis, float* __restrict__ sagg) {
    int total = g_ecnt[cidx];
    int stride = gridDim.x * blockDim.x;
    for (int e = blockIdx.x * blockDim.x + threadIdx.x; e < total; e += stride) {
        int a = src[e], b = dst[e];
        atomicAdd(sagg + b, s[a] * dis[a] * dis[b]);
    }
}

__global__ void k_score(const float* __restrict__ sagg, const float* __restrict__ s,
                        const float* __restrict__ dis, const float* __restrict__ gb,
                        float* __restrict__ score, int n) {
    int i = blockIdx.x * blockDim.x + threadIdx.x;
    if (i < n) score[i] = sagg[i] + s[i] * dis[i] * dis[i] + gb[0];
}

// ---------------- radix-select top-k ----------------
__device__ __forceinline__ unsigned ordkey(float f) {
    unsigned u = __float_as_uint(f);
    return (u & 0x80000000u) ? ~u : (u | 0x80000000u);
}

__global__ void rs_init(int k) {
    if (threadIdx.x < 256) g_hist[threadIdx.x] = 0;
    if (threadIdx.x == 0) {
        g_prefix = 0; g_kremain = k; g_tieneed = 0; g_selpos = 0; g_tietick = 0;
    }
}

__global__ void rs_hist(const float* __restrict__ sc, int n, int shift) {
    __shared__ unsigned sh[256];
    sh[threadIdx.x] = 0;
    __syncthreads();
    unsigned pref = g_prefix;
    int stride = gridDim.x * blockDim.x;
    for (int i = blockIdx.x * blockDim.x + threadIdx.x; i < n; i += stride) {
        unsigned u = ordkey(sc[i]);
        bool ok = (shift == 24) || ((u >> (shift + 8)) == (pref >> (shift + 8)));
        if (ok) atomicAdd(&sh[(u >> shift) & 255], 1u);
    }
    __syncthreads();
    if (sh[threadIdx.x]) atomicAdd(&g_hist[threadIdx.x], sh[threadIdx.x]);
}

__global__ void rs_pick(int shift) {
    if (blockIdx.x == 0 && threadIdx.x == 0) {
        int rem = g_kremain;
        for (int b = 255; b >= 0; --b) {
            int c = (int)g_hist[b];
            if (c >= rem) {
                g_prefix |= ((unsigned)b) << shift;
                g_kremain = rem;
                if (shift == 0) g_tieneed = rem;
                break;
            }
            rem -= c;
        }
        for (int b = 0; b < 256; b++) g_hist[b] = 0;
    }
}

__global__ void k_select(const float* __restrict__ score, int n) {
    unsigned T = g_prefix;
    int need = g_tieneed;
    int stride = gridDim.x * blockDim.x;
    for (int i = blockIdx.x * blockDim.x + threadIdx.x; i < n; i += stride) {
        unsigned u = ordkey(score[i]);
        if (u > T) {
            int j = atomicAdd(&g_selpos, 1);
            g_perm[j] = i; g_rank[i] = j;
        } else if (u == T) {
            int t = atomicAdd(&g_tietick, 1);
            if (t < need) {
                int j = atomicAdd(&g_selpos, 1);
                g_perm[j] = i; g_rank[i] = j;
            }
        }
    }
}

__global__ void k_gather(const float* __restrict__ h, const float* __restrict__ score,
                         float* __restrict__ hk, int k) {
    int stride = gridDim.x * blockDim.x;
    int total = k * 128;
    for (int idx = blockIdx.x * blockDim.x + threadIdx.x; idx < total; idx += stride) {
        int j = idx >> 7, f = idx & 127;
        int i = g_perm[j];
        hk[idx] = h[(size_t)i * 128 + f] * tanhf(score[i]);
    }
}

__global__ void k_ecompact(const int* __restrict__ src, const int* __restrict__ dst,
                           int cin, int cout, int* __restrict__ so, int* __restrict__ dd) {
    int total = g_ecnt[cin];
    int stride = gridDim.x * blockDim.x;
    for (int e = blockIdx.x * blockDim.x + threadIdx.x; e < total; e += stride) {
        int a = g_rank[src[e]], b = g_rank[dst[e]];
        if (a >= 0 && b >= 0) {
            int p = atomicAdd(&g_ecnt[cout], 1);
            so[p] = a; dd[p] = b;
        }
    }
}

// ---------------- global max/mean pooling ----------------
__global__ void k_pool(const float* __restrict__ hk, int k, float* __restrict__ outp) {
    __shared__ float smax[256], ssum[256];
    int f = blockIdx.x;  // 0..127
    float mx = -3.402823466e38f, sm = 0.0f;
    for (int r = threadIdx.x; r < k; r += blockDim.x) {
        float v = hk[(size_t)r * 128 + f];
        mx = fmaxf(mx, v); sm += v;
    }
    smax[threadIdx.x] = mx; ssum[threadIdx.x] = sm;
    __syncthreads();
    for (int o = 128; o; o >>= 1) {
        if (threadIdx.x < o) {
            smax[threadIdx.x] = fmaxf(smax[threadIdx.x], smax[threadIdx.x + o]);
            ssum[threadIdx.x] += ssum[threadIdx.x + o];
        }
        __syncthreads();
    }
    if (threadIdx.x == 0) {
        outp[f] = smax[0];
        outp[128 + f] = ssum[0] / (float)k;
    }
}

// ---------------- final MLP ----------------
__global__ void k_mlp(const float* __restrict__ lw1, const float* __restrict__ lb1,
                      const float* __restrict__ lw2, const float* __restrict__ lb2,
                      const float* __restrict__ lw3, const float* __restrict__ lb3,
                      float* __restrict__ out) {
    __shared__ float g[256], t1[128], t2[32];
    int tid = threadIdx.x;
    if (tid < 256) g[tid] = g_pool[tid] + g_pool[256 + tid] + g_pool[512 + tid];
    __syncthreads();
    if (tid < 128) {
        float a = lb1[tid];
        for (int i = 0; i < 256; i++) a += g[i] * lw1[i * 128 + tid];
        t1[tid] = fmaxf(a, 0.0f);
    }
    __syncthreads();
    if (tid < 32) {
        float a = lb2[tid];
        for (int i = 0; i < 128; i++) a += t1[i] * lw2[i * 32 + tid];
        float r = fmaxf(a, 0.0f);
        t2[tid] = r;
        out[tid] = r;         // features
    }
    __syncthreads();
    if (tid < 3) {
        float a = lb3[tid];
        for (int i = 0; i < 32; i++) a += t2[i] * lw3[i * 3 + tid];
        out[32 + tid] = a;    // logits
    }
}

// ---------------- orchestration ----------------
static void run_select(const float* score, int n, int k) {
    rs_init<<<1, 256>>>(k);
    const int shifts[4] = {24, 16, 8, 0};
    for (int p = 0; p < 4; p++) {
        rs_hist<<<128, 256>>>(score, n, shifts[p]);
        rs_pick<<<1, 1>>>(shifts[p]);
    }
    k_select<<<128, 256>>>(score, n);
}

extern "C" void kernel_launch(void* const* d_in, const int* in_sizes, int n_in,
                              void* d_out, int out_size) {
    const float* x   = (const float*)d_in[0];
    const int*   ei  = (const int*)d_in[1];
    const float* w1l = (const float*)d_in[2];
    const float* b1l = (const float*)d_in[3];
    const float* w1r = (const float*)d_in[4];
    const float* g1w = (const float*)d_in[5];
    const float* g1b = (const float*)d_in[6];
    const float* w2l = (const float*)d_in[7];
    const float* b2l = (const float*)d_in[8];
    const float* w2r = (const float*)d_in[9];
    const float* g2w = (const float*)d_in[10];
    const float* g2b = (const float*)d_in[11];
    const float* w3l = (const float*)d_in[12];
    const float* b3l = (const float*)d_in[13];
    const float* w3r = (const float*)d_in[14];
    const float* g3w = (const float*)d_in[15];
    const float* g3b = (const float*)d_in[16];
    const float* lw1 = (const float*)d_in[17];
    const float* lb1 = (const float*)d_in[18];
    const float* lw2 = (const float*)d_in[19];
    const float* lb2 = (const float*)d_in[20];
    const float* lw3 = (const float*)d_in[21];
    const float* lb3 = (const float*)d_in[22];
    float* out = (float*)d_out;

    const int N = in_sizes[0] / FIN;
    const int E = in_sizes[1] / 2;
    const int* src = ei;
    const int* dst = ei + E;
    const int K1 = (N + 4) / 5;
    const int K2 = (K1 + 4) / 5;
    const int K3 = (K2 + 4) / 5;

    // pointers to device globals (via a tiny symbol trick: kernels address them directly,
    // host only needs raw pointers for the generic zero kernels)
    float *p_xw, *p_h, *p_agg, *p_cnt, *p_s, *p_dis, *p_sagg, *p_score, *p_hk, *p_pool;
    int *p_rank, *p_src2, *p_dst2, *p_src3, *p_dst3;
    cudaGetSymbolAddress((void**)&p_xw,   g_xw);
    cudaGetSymbolAddress((void**)&p_h,    g_h);
    cudaGetSymbolAddress((void**)&p_agg,  g_agg);
    cudaGetSymbolAddress((void**)&p_cnt,  g_cnt);
    cudaGetSymbolAddress((void**)&p_s,    g_s);
    cudaGetSymbolAddress((void**)&p_dis,  g_dis);
    cudaGetSymbolAddress((void**)&p_sagg, g_sagg);
    cudaGetSymbolAddress((void**)&p_score,g_score);
    cudaGetSymbolAddress((void**)&p_hk,   g_hk);
    cudaGetSymbolAddress((void**)&p_pool, g_pool);
    cudaGetSymbolAddress((void**)&p_rank, g_rank);
    cudaGetSymbolAddress((void**)&p_src2, g_esrc2);
    cudaGetSymbolAddress((void**)&p_dst2, g_edst2);
    cudaGetSymbolAddress((void**)&p_src3, g_esrc3);
    cudaGetSymbolAddress((void**)&p_dst3, g_edst3);

    k_init<<<1, 32>>>(E);

    // ================= stage 1 (N nodes, input edges) =================
    {
        dim3 grid((N + 127) / 128, 2);
        k_sgemm<<<grid, 256>>>(x, w1l, w1r, p_xw, N, FIN);
    }
    k_zero_f<<<2048, 256>>>(p_agg, N * 128);
    k_zero_f<<<256, 256>>>(p_cnt, N);
    k_zero_f<<<256, 256>>>(p_sagg, N);
    k_fill_i<<<256, 256>>>(p_rank, -1, N);
    k_sage_agg<<<4096, 256>>>(src, dst, 0, p_xw, p_agg, p_cnt);
    k_h_fin<<<(N * 32 + 255) / 256, 256>>>(p_agg, p_cnt, p_xw, b1l, g1w, p_h, p_s, p_dis, N);
    k_gcn_edge<<<1024, 256>>>(src, dst, 0, p_s, p_dis, p_sagg);
    k_score<<<(N + 255) / 256, 256>>>(p_sagg, p_s, p_dis, g1b, p_score, N);
    run_select(p_score, N, K1);
    k_gather<<<(K1 * 128 + 255) / 256, 256>>>(p_h, p_score, p_hk, K1);
    k_ecompact<<<1024, 256>>>(src, dst, 0, 1, p_src2, p_dst2);
    k_pool<<<128, 256>>>(p_hk, K1, p_pool);

    // ================= stage 2 (K1 nodes, compacted edges) =================
    {
        dim3 grid((K1 + 127) / 128, 2);
        k_sgemm<<<grid, 256>>>(p_hk, w2l, w2r, p_xw, K1, NH);
    }
    k_zero_f<<<1024, 256>>>(p_agg, K1 * 128);
    k_zero_f<<<64, 256>>>(p_cnt, K1);
    k_zero_f<<<64, 256>>>(p_sagg, K1);
    k_fill_i<<<64, 256>>>(p_rank, -1, K1);
    k_sage_agg<<<1024, 256>>>(p_src2, p_dst2, 1, p_xw, p_agg, p_cnt);
    k_h_fin<<<(K1 * 32 + 255) / 256, 256>>>(p_agg, p_cnt, p_xw, b2l, g2w, p_h, p_s, p_dis, K1);
    k_gcn_edge<<<256, 256>>>(p_src2, p_dst2, 1, p_s, p_dis, p_sagg);
    k_score<<<(K1 + 255) / 256, 256>>>(p_sagg, p_s, p_dis, g2b, p_score, K1);
    run_select(p_score, K1, K2);
    k_gather<<<(K2 * 128 + 255) / 256, 256>>>(p_h, p_score, p_hk, K2);
    k_ecompact<<<256, 256>>>(p_src2, p_dst2, 1, 2, p_src3, p_dst3);
    k_pool<<<128, 256>>>(p_hk, K2, p_pool + 256);

    // ================= stage 3 (K2 nodes) =================
    {
        dim3 grid((K2 + 127) / 128, 2);
        k_sgemm<<<grid, 256>>>(p_hk, w3l, w3r, p_xw, K2, NH);
    }
    k_zero_f<<<256, 256>>>(p_agg, K2 * 128);
    k_zero_f<<<16, 256>>>(p_cnt, K2);
    k_zero_f<<<16, 256>>>(p_sagg, K2);
    k_fill_i<<<16, 256>>>(p_rank, -1, K2);
    k_sage_agg<<<256, 256>>>(p_src3, p_dst3, 2, p_xw, p_agg, p_cnt);
    k_h_fin<<<(K2 * 32 + 255) / 256, 256>>>(p_agg, p_cnt, p_xw, b3l, g3w, p_h, p_s, p_dis, K2);
    k_gcn_edge<<<64, 256>>>(p_src3, p_dst3, 2, p_s, p_dis, p_sagg);
    k_score<<<(K2 + 255) / 256, 256>>>(p_sagg, p_s, p_dis, g3b, p_score, K2);
    run_select(p_score, K2, K3);
    k_gather<<<(K3 * 128 + 255) / 256, 256>>>(p_h, p_score, p_hk, K3);
    k_pool<<<128, 256>>>(p_hk, K3, p_pool + 512);

    // ================= readout MLP =================
    k_mlp<<<1, 256>>>(lw1, lb1, lw2, lb2, lw3, lb3, out);
}

// round 2
// speedup vs baseline: 1.3869x; 1.3869x over previous
#include <cuda_runtime.h>
#include <cuda_bf16.h>
#include <math.h>

// ---------------- problem constants ----------------
#define NMAX 100000
#define EMAX 500000
#define FIN  512
#define NH   128

// ---------------- device scratch (static, no allocs) ----------------
__device__ __align__(16) float g_xw [NMAX * 256];   // [xl | xr] per node
__device__ __align__(16) float g_h  [NMAX * NH];    // sage output (post relu)
__device__ __align__(16) float g_agg[NMAX * NH];    // neighbor aggregate
__device__ float g_cnt [NMAX];
__device__ float g_s   [NMAX];                       // gcn xw scalar
__device__ float g_dis [NMAX];                       // rsqrt(deg)
__device__ float g_sagg[NMAX];
__device__ float g_score[NMAX];
__device__ int   g_rank[NMAX];
__device__ int   g_perm[NMAX];
__device__ __align__(16) float g_hk[20000 * NH];     // pooled features (max K1)
__device__ int g_esrc2[EMAX], g_edst2[EMAX];
__device__ int g_esrc3[EMAX], g_edst3[EMAX];
__device__ float g_pool[3 * 256];                    // x1,x2,x3 : [max128|mean128]

// radix-select / counters
__device__ unsigned g_hist[256];
__device__ unsigned g_prefix;
__device__ int g_kremain, g_tieneed, g_selpos, g_tietick;
__device__ int g_ecnt[4];   // [0]=E (layer1), [1]=after pool1, [2]=after pool2

// ---------------- utility kernels ----------------
__global__ void k_init(int E) {
    if (blockIdx.x == 0 && threadIdx.x == 0) {
        g_ecnt[0] = E; g_ecnt[1] = 0; g_ecnt[2] = 0; g_ecnt[3] = 0;
    }
}

__global__ void k_zero_f(float* p, int n) {
    for (int i = blockIdx.x * blockDim.x + threadIdx.x; i < n; i += gridDim.x * blockDim.x)
        p[i] = 0.0f;
}

__global__ void k_fill_i(int* p, int v, int n) {
    for (int i = blockIdx.x * blockDim.x + threadIdx.x; i < n; i += gridDim.x * blockDim.x)
        p[i] = v;
}

// ---------------- tensor-core bf16x3 GEMM ----------------
// C[:,0:128]=A@B1 (grid.y=0), C[:,128:256]=A@B2 (grid.y=1)
// A row-major [M,K] fp32, B row-major [K,128] fp32, C row-major [M,256] fp32.
// Split each fp32 into bf16 hi+lo; compute AhBh + AlBh + AhBl (fp32 accum).
#define MMA_BF16(D, Ar, Br)                                                  \
    asm volatile(                                                            \
        "mma.sync.aligned.m16n8k16.row.col.f32.bf16.bf16.f32 "               \
        "{%0,%1,%2,%3}, {%4,%5,%6,%7}, {%8,%9}, {%0,%1,%2,%3};\n"            \
        : "+f"(D[0]), "+f"(D[1]), "+f"(D[2]), "+f"(D[3])                     \
        : "r"(Ar[0]), "r"(Ar[1]), "r"(Ar[2]), "r"(Ar[3]),                    \
          "r"(Br[0]), "r"(Br[1]))

__global__ __launch_bounds__(256)
void k_tcgemm(const float* __restrict__ A, const float* __restrict__ B1,
              const float* __restrict__ B2, float* __restrict__ C,
              int M, int K) {
    __shared__ __nv_bfloat16 sAh[128][18], sAl[128][18];
    __shared__ __nv_bfloat16 sBh[128][18], sBl[128][18];   // transposed: [n][k]

    const float* B = (blockIdx.y == 0) ? B1 : B2;
    const int bm   = blockIdx.x * 128;
    const int tid  = threadIdx.x;
    const int lane = tid & 31;
    const int w    = tid >> 5;
    const int wm   = (w & 3) * 32;     // warp m offset (4 warps in m)
    const int wn   = (w >> 2) * 64;    // warp n offset (2 warps in n)
    const int g    = lane >> 2;        // 0..7
    const int q    = lane & 3;         // 0..3

    // global load mapping
    const int ar = tid >> 1;           // A row within tile 0..127
    const int ac = (tid & 1) * 8;      // A col 0 or 8
    const int bk = tid & 15;           // B row (k) within chunk
    const int bc = (tid >> 4) * 8;     // B col 0..120

    const int gmA = bm + ar;
    const bool aval = (gmA < M);
    const float* Aptr = aval ? (A + (size_t)gmA * K + ac) : A;

    float c[2][8][4];
#pragma unroll
    for (int i = 0; i < 2; i++)
#pragma unroll
        for (int j = 0; j < 8; j++)
#pragma unroll
            for (int r = 0; r < 4; r++) c[i][j][r] = 0.0f;

    const int nch = K >> 4;
    float4 pa0, pa1, pb0, pb1;
    // prefetch chunk 0
    {
        pa0 = aval ? *(const float4*)(Aptr + 0) : make_float4(0, 0, 0, 0);
        pa1 = aval ? *(const float4*)(Aptr + 4) : make_float4(0, 0, 0, 0);
        const float* bp = B + (size_t)bk * 128 + bc;
        pb0 = *(const float4*)(bp + 0);
        pb1 = *(const float4*)(bp + 4);
    }

    for (int ch = 0; ch < nch; ch++) {
        // ---- convert + store current chunk to smem ----
        {
            float av[8] = {pa0.x, pa0.y, pa0.z, pa0.w, pa1.x, pa1.y, pa1.z, pa1.w};
#pragma unroll
            for (int i = 0; i < 8; i++) {
                __nv_bfloat16 h = __float2bfloat16(av[i]);
                sAh[ar][ac + i] = h;
                sAl[ar][ac + i] = __float2bfloat16(av[i] - __bfloat162float(h));
            }
            float bv[8] = {pb0.x, pb0.y, pb0.z, pb0.w, pb1.x, pb1.y, pb1.z, pb1.w};
#pragma unroll
            for (int i = 0; i < 8; i++) {
                __nv_bfloat16 h = __float2bfloat16(bv[i]);
                sBh[bc + i][bk] = h;
                sBl[bc + i][bk] = __float2bfloat16(bv[i] - __bfloat162float(h));
            }
        }
        __syncthreads();

        // ---- prefetch next chunk ----
        if (ch + 1 < nch) {
            const float* ap = Aptr + (ch + 1) * 16;
            pa0 = aval ? *(const float4*)(ap + 0) : make_float4(0, 0, 0, 0);
            pa1 = aval ? *(const float4*)(ap + 4) : make_float4(0, 0, 0, 0);
            const float* bp = B + (size_t)((ch + 1) * 16 + bk) * 128 + bc;
            pb0 = *(const float4*)(bp + 0);
            pb1 = *(const float4*)(bp + 4);
        }

        // ---- compute: load B frags once, loop A tiles ----
        unsigned bH[8][2], bL[8][2];
#pragma unroll
        for (int j = 0; j < 8; j++) {
            int col = wn + j * 8 + g;
            bH[j][0] = *(const unsigned*)&sBh[col][q * 2];
            bH[j][1] = *(const unsigned*)&sBh[col][q * 2 + 8];
            bL[j][0] = *(const unsigned*)&sBl[col][q * 2];
            bL[j][1] = *(const unsigned*)&sBl[col][q * 2 + 8];
        }
#pragma unroll
        for (int i = 0; i < 2; i++) {
            int rb = wm + i * 16;
            unsigned aH[4], aL[4];
            aH[0] = *(const unsigned*)&sAh[rb + g][q * 2];
            aH[1] = *(const unsigned*)&sAh[rb + 8 + g][q * 2];
            aH[2] = *(const unsigned*)&sAh[rb + g][q * 2 + 8];
            aH[3] = *(const unsigned*)&sAh[rb + 8 + g][q * 2 + 8];
            aL[0] = *(const unsigned*)&sAl[rb + g][q * 2];
            aL[1] = *(const unsigned*)&sAl[rb + 8 + g][q * 2];
            aL[2] = *(const unsigned*)&sAl[rb + g][q * 2 + 8];
            aL[3] = *(const unsigned*)&sAl[rb + 8 + g][q * 2 + 8];
#pragma unroll
            for (int j = 0; j < 8; j++) {
                MMA_BF16(c[i][j], aH, bH[j]);
                MMA_BF16(c[i][j], aL, bH[j]);
                MMA_BF16(c[i][j], aH, bL[j]);
            }
        }
        __syncthreads();
    }

    // ---- writeback ----
    const int ncol0 = blockIdx.y * 128 + wn;
#pragma unroll
    for (int i = 0; i < 2; i++) {
        int r0 = bm + wm + i * 16 + g;
        int r1 = r0 + 8;
#pragma unroll
        for (int j = 0; j < 8; j++) {
            int col = ncol0 + j * 8 + q * 2;
            if (r0 < M) *(float2*)&C[(size_t)r0 * 256 + col] = make_float2(c[i][j][0], c[i][j][1]);
            if (r1 < M) *(float2*)&C[(size_t)r1 * 256 + col] = make_float2(c[i][j][2], c[i][j][3]);
        }
    }
}

// ---------------- SAGE neighbor aggregation (128-dim, post-GEMM) ----------------
__global__ void k_sage_agg(const int* __restrict__ src, const int* __restrict__ dst,
                           int cidx, const float* __restrict__ xw,
                           float* __restrict__ agg, float* __restrict__ cnt) {
    long total = (long)g_ecnt[cidx] * 32;
    long stride = (long)gridDim.x * blockDim.x;
    for (long idx = (long)blockIdx.x * blockDim.x + threadIdx.x; idx < total; idx += stride) {
        int e = (int)(idx >> 5);
        int c = (int)(idx & 31) << 2;
        int s = src[e], d = dst[e];
        float4 v = *(const float4*)(xw + (size_t)s * 256 + c);
        float* p = agg + (size_t)d * 128 + c;
        asm volatile("red.global.add.v4.f32 [%0], {%1,%2,%3,%4};"
                     :: "l"(p), "f"(v.x), "f"(v.y), "f"(v.z), "f"(v.w)
                     : "memory");
        if (c == 0) atomicAdd(cnt + d, 1.0f);
    }
}

// ---------------- h = relu(agg/max(cnt,1)+bl+xr); s = h.gw; dis = rsqrt(cnt+1) ----------------
__global__ void k_h_fin(const float* __restrict__ agg, const float* __restrict__ cnt,
                        const float* __restrict__ xw, const float* __restrict__ bl,
                        const float* __restrict__ gw, float* __restrict__ h,
                        float* __restrict__ s, float* __restrict__ dis, int n) {
    int w = (blockIdx.x * blockDim.x + threadIdx.x) >> 5;
    int lane = threadIdx.x & 31;
    if (w >= n) return;
    float c = cnt[w];
    float inv = 1.0f / fmaxf(c, 1.0f);
    float part = 0.0f;
#pragma unroll
    for (int f = lane; f < 128; f += 32) {
        float v = agg[(size_t)w * 128 + f] * inv + bl[f] + xw[(size_t)w * 256 + 128 + f];
        v = fmaxf(v, 0.0f);
        h[(size_t)w * 128 + f] = v;
        part += v * gw[f];
    }
#pragma unroll
    for (int o = 16; o; o >>= 1) part += __shfl_down_sync(0xffffffffu, part, o);
    if (lane == 0) { s[w] = part; dis[w] = rsqrtf(c + 1.0f); }
}

// ---------------- GCN score edge pass ----------------
__global__ void k_gcn_edge(const int* __restrict__ src, const int* __restrict__ dst,
                           int cidx, const float* __restrict__ s,
                           const float* __restrict__ dis, float* __restrict__ sagg) {
    int total = g_ecnt[cidx];
    int stride = gridDim.x * blockDim.x;
    for (int e = blockIdx.x * blockDim.x + threadIdx.x; e < total; e += stride) {
        int a = src[e], b = dst[e];
        atomicAdd(sagg + b, s[a] * dis[a] * dis[b]);
    }
}

__global__ void k_score(const float* __restrict__ sagg, const float* __restrict__ s,
                        const float* __restrict__ dis, const float* __restrict__ gb,
                        float* __restrict__ score, int n) {
    int i = blockIdx.x * blockDim.x + threadIdx.x;
    if (i < n) score[i] = sagg[i] + s[i] * dis[i] * dis[i] + gb[0];
}

// ---------------- radix-select top-k ----------------
__device__ __forceinline__ unsigned ordkey(float f) {
    unsigned u = __float_as_uint(f);
    return (u & 0x80000000u) ? ~u : (u | 0x80000000u);
}

__global__ void rs_init(int k) {
    if (threadIdx.x < 256) g_hist[threadIdx.x] = 0;
    if (threadIdx.x == 0) {
        g_prefix = 0; g_kremain = k; g_tieneed = 0; g_selpos = 0; g_tietick = 0;
    }
}

__global__ void rs_hist(const float* __restrict__ sc, int n, int shift) {
    __shared__ unsigned sh[256];
    sh[threadIdx.x] = 0;
    __syncthreads();
    unsigned pref = g_prefix;
    int stride = gridDim.x * blockDim.x;
    for (int i = blockIdx.x * blockDim.x + threadIdx.x; i < n; i += stride) {
        unsigned u = ordkey(sc[i]);
        bool ok = (shift == 24) || ((u >> (shift + 8)) == (pref >> (shift + 8)));
        if (ok) atomicAdd(&sh[(u >> shift) & 255], 1u);
    }
    __syncthreads();
    if (sh[threadIdx.x]) atomicAdd(&g_hist[threadIdx.x], sh[threadIdx.x]);
}

__global__ void rs_pick(int shift) {
    if (blockIdx.x == 0 && threadIdx.x == 0) {
        int rem = g_kremain;
        for (int b = 255; b >= 0; --b) {
            int c = (int)g_hist[b];
            if (c >= rem) {
                g_prefix |= ((unsigned)b) << shift;
                g_kremain = rem;
                if (shift == 0) g_tieneed = rem;
                break;
            }
            rem -= c;
        }
        for (int b = 0; b < 256; b++) g_hist[b] = 0;
    }
}

__global__ void k_select(const float* __restrict__ score, int n) {
    unsigned T = g_prefix;
    int need = g_tieneed;
    int stride = gridDim.x * blockDim.x;
    for (int i = blockIdx.x * blockDim.x + threadIdx.x; i < n; i += stride) {
        unsigned u = ordkey(score[i]);
        if (u > T) {
            int j = atomicAdd(&g_selpos, 1);
            g_perm[j] = i; g_rank[i] = j;
        } else if (u == T) {
            int t = atomicAdd(&g_tietick, 1);
            if (t < need) {
                int j = atomicAdd(&g_selpos, 1);
                g_perm[j] = i; g_rank[i] = j;
            }
        }
    }
}

__global__ void k_gather(const float* __restrict__ h, const float* __restrict__ score,
                         float* __restrict__ hk, int k) {
    int stride = gridDim.x * blockDim.x;
    int total = k * 128;
    for (int idx = blockIdx.x * blockDim.x + threadIdx.x; idx < total; idx += stride) {
        int j = idx >> 7, f = idx & 127;
        int i = g_perm[j];
        hk[idx] = h[(size_t)i * 128 + f] * tanhf(score[i]);
    }
}

__global__ void k_ecompact(const int* __restrict__ src, const int* __restrict__ dst,
                           int cin, int cout, int* __restrict__ so, int* __restrict__ dd) {
    int total = g_ecnt[cin];
    int stride = gridDim.x * blockDim.x;
    for (int e = blockIdx.x * blockDim.x + threadIdx.x; e < total; e += stride) {
        int a = g_rank[src[e]], b = g_rank[dst[e]];
        if (a >= 0 && b >= 0) {
            int p = atomicAdd(&g_ecnt[cout], 1);
            so[p] = a; dd[p] = b;
        }
    }
}

// ---------------- global max/mean pooling ----------------
__global__ void k_pool(const float* __restrict__ hk, int k, float* __restrict__ outp) {
    __shared__ float smax[256], ssum[256];
    int f = blockIdx.x;  // 0..127
    float mx = -3.402823466e38f, sm = 0.0f;
    for (int r = threadIdx.x; r < k; r += blockDim.x) {
        float v = hk[(size_t)r * 128 + f];
        mx = fmaxf(mx, v); sm += v;
    }
    smax[threadIdx.x] = mx; ssum[threadIdx.x] = sm;
    __syncthreads();
    for (int o = 128; o; o >>= 1) {
        if (threadIdx.x < o) {
            smax[threadIdx.x] = fmaxf(smax[threadIdx.x], smax[threadIdx.x + o]);
            ssum[threadIdx.x] += ssum[threadIdx.x + o];
        }
        __syncthreads();
    }
    if (threadIdx.x == 0) {
        outp[f] = smax[0];
        outp[128 + f] = ssum[0] / (float)k;
    }
}

// ---------------- final MLP ----------------
__global__ void k_mlp(const float* __restrict__ lw1, const float* __restrict__ lb1,
                      const float* __restrict__ lw2, const float* __restrict__ lb2,
                      const float* __restrict__ lw3, const float* __restrict__ lb3,
                      float* __restrict__ out) {
    __shared__ float g[256], t1[128], t2[32];
    int tid = threadIdx.x;
    if (tid < 256) g[tid] = g_pool[tid] + g_pool[256 + tid] + g_pool[512 + tid];
    __syncthreads();
    if (tid < 128) {
        float a = lb1[tid];
        for (int i = 0; i < 256; i++) a += g[i] * lw1[i * 128 + tid];
        t1[tid] = fmaxf(a, 0.0f);
    }
    __syncthreads();
    if (tid < 32) {
        float a = lb2[tid];
        for (int i = 0; i < 128; i++) a += t1[i] * lw2[i * 32 + tid];
        float r = fmaxf(a, 0.0f);
        t2[tid] = r;
        out[tid] = r;         // features
    }
    __syncthreads();
    if (tid < 3) {
        float a = lb3[tid];
        for (int i = 0; i < 32; i++) a += t2[i] * lw3[i * 3 + tid];
        out[32 + tid] = a;    // logits
    }
}

// ---------------- orchestration ----------------
static void run_select(const float* score, int n, int k) {
    rs_init<<<1, 256>>>(k);
    const int shifts[4] = {24, 16, 8, 0};
    for (int p = 0; p < 4; p++) {
        rs_hist<<<128, 256>>>(score, n, shifts[p]);
        rs_pick<<<1, 1>>>(shifts[p]);
    }
    k_select<<<128, 256>>>(score, n);
}

extern "C" void kernel_launch(void* const* d_in, const int* in_sizes, int n_in,
                              void* d_out, int out_size) {
    const float* x   = (const float*)d_in[0];
    const int*   ei  = (const int*)d_in[1];
    const float* w1l = (const float*)d_in[2];
    const float* b1l = (const float*)d_in[3];
    const float* w1r = (const float*)d_in[4];
    const float* g1w = (const float*)d_in[5];
    const float* g1b = (const float*)d_in[6];
    const float* w2l = (const float*)d_in[7];
    const float* b2l = (const float*)d_in[8];
    const float* w2r = (const float*)d_in[9];
    const float* g2w = (const float*)d_in[10];
    const float* g2b = (const float*)d_in[11];
    const float* w3l = (const float*)d_in[12];
    const float* b3l = (const float*)d_in[13];
    const float* w3r = (const float*)d_in[14];
    const float* g3w = (const float*)d_in[15];
    const float* g3b = (const float*)d_in[16];
    const float* lw1 = (const float*)d_in[17];
    const float* lb1 = (const float*)d_in[18];
    const float* lw2 = (const float*)d_in[19];
    const float* lb2 = (const float*)d_in[20];
    const float* lw3 = (const float*)d_in[21];
    const float* lb3 = (const float*)d_in[22];
    float* out = (float*)d_out;

    const int N = in_sizes[0] / FIN;
    const int E = in_sizes[1] / 2;
    const int* src = ei;
    const int* dst = ei + E;
    const int K1 = (N + 4) / 5;
    const int K2 = (K1 + 4) / 5;
    const int K3 = (K2 + 4) / 5;

    float *p_xw, *p_h, *p_agg, *p_cnt, *p_s, *p_dis, *p_sagg, *p_score, *p_hk, *p_pool;
    int *p_rank, *p_src2, *p_dst2, *p_src3, *p_dst3;
    cudaGetSymbolAddress((void**)&p_xw,   g_xw);
    cudaGetSymbolAddress((void**)&p_h,    g_h);
    cudaGetSymbolAddress((void**)&p_agg,  g_agg);
    cudaGetSymbolAddress((void**)&p_cnt,  g_cnt);
    cudaGetSymbolAddress((void**)&p_s,    g_s);
    cudaGetSymbolAddress((void**)&p_dis,  g_dis);
    cudaGetSymbolAddress((void**)&p_sagg, g_sagg);
    cudaGetSymbolAddress((void**)&p_score,g_score);
    cudaGetSymbolAddress((void**)&p_hk,   g_hk);
    cudaGetSymbolAddress((void**)&p_pool, g_pool);
    cudaGetSymbolAddress((void**)&p_rank, g_rank);
    cudaGetSymbolAddress((void**)&p_src2, g_esrc2);
    cudaGetSymbolAddress((void**)&p_dst2, g_edst2);
    cudaGetSymbolAddress((void**)&p_src3, g_esrc3);
    cudaGetSymbolAddress((void**)&p_dst3, g_edst3);

    k_init<<<1, 32>>>(E);

    // ================= stage 1 (N nodes, input edges) =================
    {
        dim3 grid((N + 127) / 128, 2);
        k_tcgemm<<<grid, 256>>>(x, w1l, w1r, p_xw, N, FIN);
    }
    k_zero_f<<<2048, 256>>>(p_agg, N * 128);
    k_zero_f<<<256, 256>>>(p_cnt, N);
    k_zero_f<<<256, 256>>>(p_sagg, N);
    k_fill_i<<<256, 256>>>(p_rank, -1, N);
    k_sage_agg<<<4096, 256>>>(src, dst, 0, p_xw, p_agg, p_cnt);
    k_h_fin<<<(N * 32 + 255) / 256, 256>>>(p_agg, p_cnt, p_xw, b1l, g1w, p_h, p_s, p_dis, N);
    k_gcn_edge<<<1024, 256>>>(src, dst, 0, p_s, p_dis, p_sagg);
    k_score<<<(N + 255) / 256, 256>>>(p_sagg, p_s, p_dis, g1b, p_score, N);
    run_select(p_score, N, K1);
    k_gather<<<(K1 * 128 + 255) / 256, 256>>>(p_h, p_score, p_hk, K1);
    k_ecompact<<<1024, 256>>>(src, dst, 0, 1, p_src2, p_dst2);
    k_pool<<<128, 256>>>(p_hk, K1, p_pool);

    // ================= stage 2 (K1 nodes, compacted edges) =================
    {
        dim3 grid((K1 + 127) / 128, 2);
        k_tcgemm<<<grid, 256>>>(p_hk, w2l, w2r, p_xw, K1, NH);
    }
    k_zero_f<<<1024, 256>>>(p_agg, K1 * 128);
    k_zero_f<<<64, 256>>>(p_cnt, K1);
    k_zero_f<<<64, 256>>>(p_sagg, K1);
    k_fill_i<<<64, 256>>>(p_rank, -1, K1);
    k_sage_agg<<<1024, 256>>>(p_src2, p_dst2, 1, p_xw, p_agg, p_cnt);
    k_h_fin<<<(K1 * 32 + 255) / 256, 256>>>(p_agg, p_cnt, p_xw, b2l, g2w, p_h, p_s, p_dis, K1);
    k_gcn_edge<<<256, 256>>>(p_src2, p_dst2, 1, p_s, p_dis, p_sagg);
    k_score<<<(K1 + 255) / 256, 256>>>(p_sagg, p_s, p_dis, g2b, p_score, K1);
    run_select(p_score, K1, K2);
    k_gather<<<(K2 * 128 + 255) / 256, 256>>>(p_h, p_score, p_hk, K2);
    k_ecompact<<<256, 256>>>(p_src2, p_dst2, 1, 2, p_src3, p_dst3);
    k_pool<<<128, 256>>>(p_hk, K2, p_pool + 256);

    // ================= stage 3 (K2 nodes) =================
    {
        dim3 grid((K2 + 127) / 128, 2);
        k_tcgemm<<<grid, 256>>>(p_hk, w3l, w3r, p_xw, K2, NH);
    }
    k_zero_f<<<256, 256>>>(p_agg, K2 * 128);
    k_zero_f<<<16, 256>>>(p_cnt, K2);
    k_zero_f<<<16, 256>>>(p_sagg, K2);
    k_fill_i<<<16, 256>>>(p_rank, -1, K2);
    k_sage_agg<<<256, 256>>>(p_src3, p_dst3, 2, p_xw, p_agg, p_cnt);
    k_h_fin<<<(K2 * 32 + 255) / 256, 256>>>(p_agg, p_cnt, p_xw, b3l, g3w, p_h, p_s, p_dis, K2);
    k_gcn_edge<<<64, 256>>>(p_src3, p_dst3, 2, p_s, p_dis, p_sagg);
    k_score<<<(K2 + 255) / 256, 256>>>(p_sagg, p_s, p_dis, g3b, p_score, K2);
    run_select(p_score, K2, K3);
    k_gather<<<(K3 * 128 + 255) / 256, 256>>>(p_h, p_score, p_hk, K3);
    k_pool<<<128, 256>>>(p_hk, K3, p_pool + 512);

    // ================= readout MLP =================
    k_mlp<<<1, 256>>>(lw1, lb1, lw2, lb2, lw3, lb3, out);
}